// round 4
// baseline (speedup 1.0000x reference)
#include <cuda_runtime.h>

// Problem dims (fixed by the dataset): pred [8,4,256,256] f32, target [8,256,256] i32,
// boundary_weight [8,1,256,256] f32, output: scalar f32.
#define BQ 8
#define HQ 256
#define WQ 256
#define HWQ (HQ * WQ)
#define NPIX (BQ * HWQ)
#define BIGD2 (1 << 28)

// Scratch: __device__ globals only (harness-sanctioned). All fully overwritten
// every run -> no init kernel needed, fully deterministic.
__device__ int   g_counts[BQ * 3];     // pixel count of class c (c=1..3) per image
__device__ float g_partial[BQ * HQ];   // one partial sum per block of main kernel

// ---------------------------------------------------------------------------
// Kernel 1: per-image class counts (for degenerate-class detection).
// Grid: 8 blocks (one per image), 256 threads (one per column).
// Reads are fully coalesced (warp spans consecutive j at each row step).
// ---------------------------------------------------------------------------
__global__ void cwbl_counts_kernel(const int* __restrict__ target) {
    const int b = blockIdx.x;
    const int j = threadIdx.x;
    const int* tb = target + b * HWQ;

    int c1 = 0, c2 = 0, c3 = 0;
#pragma unroll 8
    for (int r = 0; r < HQ; ++r) {
        int v = tb[r * WQ + j];
        c1 += (v == 1);
        c2 += (v == 2);
        c3 += (v == 3);
    }
#pragma unroll
    for (int o = 16; o > 0; o >>= 1) {
        c1 += __shfl_down_sync(0xffffffffu, c1, o);
        c2 += __shfl_down_sync(0xffffffffu, c2, o);
        c3 += __shfl_down_sync(0xffffffffu, c3, o);
    }
    __shared__ int s1[8], s2[8], s3[8];
    const int wid = j >> 5, lid = j & 31;
    if (lid == 0) { s1[wid] = c1; s2[wid] = c2; s3[wid] = c3; }
    __syncthreads();
    if (j == 0) {
        int t1 = 0, t2 = 0, t3 = 0;
#pragma unroll
        for (int k = 0; k < 8; ++k) { t1 += s1[k]; t2 += s2[k]; t3 += s3[k]; }
        g_counts[b * 3 + 0] = t1;
        g_counts[b * 3 + 1] = t2;
        g_counts[b * 3 + 2] = t3;
    }
}

// ---------------------------------------------------------------------------
// Kernel 2: fused softmax + exact nearest-opposite-class distance (expanding
// Chebyshev-ring search) + weighted-error accumulation.
// Grid: 2048 blocks (one per (b, row i)), 256 threads (one per column j).
//
// Exactness: for output pixel p and class c,
//   dist_c(p) = edt(m_c)(p) + edt(~m_c)(p)
//             = sqrt(d2 to nearest pixel with target==c)   if target(p) != c
//             = sqrt(d2 to nearest pixel with target!=c)   if target(p) == c
// Ring r only contains pixels with d2 >= r*r, so once r*r >= every needed
// best-d2, the search is provably complete. Degenerate classes contribute 0
// and are excluded from the termination requirement.
// ---------------------------------------------------------------------------
__global__ void cwbl_main_kernel(const float* __restrict__ pred,
                                 const int*   __restrict__ target,
                                 const float* __restrict__ wgt) {
    const int bi = blockIdx.x;      // b*HQ + i
    const int b  = bi >> 8;
    const int i  = bi & (HQ - 1);
    const int j  = threadIdx.x;

    const int* tb  = target + b * HWQ;
    const int base = i * WQ + j;

    const int   t = tb[base];
    const float w = wgt[b * HWQ + base];

    // --- softmax over 4 channels ---
    const float* pb = pred + (size_t)b * 4 * HWQ;
    const float x0 = pb[base];
    const float x1 = pb[HWQ + base];
    const float x2 = pb[2 * HWQ + base];
    const float x3 = pb[3 * HWQ + base];
    const float mx = fmaxf(fmaxf(x0, x1), fmaxf(x2, x3));
    const float e0 = __expf(x0 - mx);
    const float e1 = __expf(x1 - mx);
    const float e2 = __expf(x2 - mx);
    const float e3 = __expf(x3 - mx);
    const float rd = 1.0f / (e0 + e1 + e2 + e3);

    // --- degenerate-class flags ---
    const int cnt1 = g_counts[b * 3 + 0];
    const int cnt2 = g_counts[b * 3 + 1];
    const int cnt3 = g_counts[b * 3 + 2];
    const bool deg1 = (cnt1 == 0) || (cnt1 == HWQ);
    const bool deg2 = (cnt2 == 0) || (cnt2 == HWQ);
    const bool deg3 = (cnt3 == 0) || (cnt3 == HWQ);

    // --- expanding ring search for nearest pixel of each class value ---
    int bd0 = BIGD2, bd1 = BIGD2, bd2 = BIGD2, bd3 = BIGD2;
    if      (t == 0) bd0 = 0;
    else if (t == 1) bd1 = 0;
    else if (t == 2) bd2 = 0;
    else             bd3 = 0;

#pragma unroll 1
    for (int r = 1; r < 256; ++r) {
        // nearest pixel of a class != t (needed when t is the class itself)
        int mo = BIGD2;
        if (t != 0) mo = min(mo, bd0);
        if (t != 1) mo = min(mo, bd1);
        if (t != 2) mo = min(mo, bd2);
        if (t != 3) mo = min(mo, bd3);

        int M = 0;
        if (!deg1) M = max(M, (t == 1) ? mo : bd1);
        if (!deg2) M = max(M, (t == 2) ? mo : bd2);
        if (!deg3) M = max(M, (t == 3) ? mo : bd3);
        if (r * r >= M) break;

        const int r2   = r * r;
        const int itop = i - r;
        const int ibot = i + r;
        const bool okT = (itop >= 0);
        const bool okB = (ibot < HQ);
        const int* rowT = tb + itop * WQ;
        const int* rowB = tb + ibot * WQ;

        // top & bottom rows of the ring
#pragma unroll 1
        for (int dj = -r; dj <= r; ++dj) {
            const int jj = j + dj;
            if ((unsigned)jj >= (unsigned)WQ) continue;
            const int d2 = r2 + dj * dj;
            if (okT) {
                const int v = __ldg(&rowT[jj]);
                bd0 = min(bd0, (v == 0) ? d2 : BIGD2);
                bd1 = min(bd1, (v == 1) ? d2 : BIGD2);
                bd2 = min(bd2, (v == 2) ? d2 : BIGD2);
                bd3 = min(bd3, (v == 3) ? d2 : BIGD2);
            }
            if (okB) {
                const int v = __ldg(&rowB[jj]);
                bd0 = min(bd0, (v == 0) ? d2 : BIGD2);
                bd1 = min(bd1, (v == 1) ? d2 : BIGD2);
                bd2 = min(bd2, (v == 2) ? d2 : BIGD2);
                bd3 = min(bd3, (v == 3) ? d2 : BIGD2);
            }
        }

        // left & right columns of the ring (excluding corners)
        const int jl = j - r;
        const int jr = j + r;
        const bool okL = (jl >= 0);
        const bool okR = (jr < WQ);
#pragma unroll 1
        for (int di = -r + 1; di <= r - 1; ++di) {
            const int ii = i + di;
            if ((unsigned)ii >= (unsigned)HQ) continue;
            const int d2  = di * di + r2;
            const int* row = tb + ii * WQ;
            if (okL) {
                const int v = __ldg(&row[jl]);
                bd0 = min(bd0, (v == 0) ? d2 : BIGD2);
                bd1 = min(bd1, (v == 1) ? d2 : BIGD2);
                bd2 = min(bd2, (v == 2) ? d2 : BIGD2);
                bd3 = min(bd3, (v == 3) ? d2 : BIGD2);
            }
            if (okR) {
                const int v = __ldg(&row[jr]);
                bd0 = min(bd0, (v == 0) ? d2 : BIGD2);
                bd1 = min(bd1, (v == 1) ? d2 : BIGD2);
                bd2 = min(bd2, (v == 2) ? d2 : BIGD2);
                bd3 = min(bd3, (v == 3) ? d2 : BIGD2);
            }
        }
    }

    // final min-over-others (for pixels whose own class is being scored)
    int mo = BIGD2;
    if (t != 0) mo = min(mo, bd0);
    if (t != 1) mo = min(mo, bd1);
    if (t != 2) mo = min(mo, bd2);
    if (t != 3) mo = min(mo, bd3);

    // --- loss contributions for classes 1..3 ---
    float acc = 0.0f;
    {
        const float dist = deg1 ? 0.0f : sqrtf((float)((t == 1) ? mo : bd1));
        const float tc = (t == 1) ? 1.0f : 0.0f;
        acc += fabsf(e1 * rd - tc) * dist;
    }
    {
        const float dist = deg2 ? 0.0f : sqrtf((float)((t == 2) ? mo : bd2));
        const float tc = (t == 2) ? 1.0f : 0.0f;
        acc += fabsf(e2 * rd - tc) * dist;
    }
    {
        const float dist = deg3 ? 0.0f : sqrtf((float)((t == 3) ? mo : bd3));
        const float tc = (t == 3) ? 1.0f : 0.0f;
        acc += fabsf(e3 * rd - tc) * dist;
    }
    acc *= w;

    // --- block reduction -> deterministic per-block partial (no atomics) ---
#pragma unroll
    for (int o = 16; o > 0; o >>= 1)
        acc += __shfl_down_sync(0xffffffffu, acc, o);
    __shared__ float sa[8];
    const int wid = j >> 5, lid = j & 31;
    if (lid == 0) sa[wid] = acc;
    __syncthreads();
    if (j == 0) {
        float s = 0.0f;
#pragma unroll
        for (int k = 0; k < 8; ++k) s += sa[k];
        g_partial[blockIdx.x] = s;
    }
}

// ---------------------------------------------------------------------------
// Kernel 3: deterministic final reduction of 2048 partials.
// ---------------------------------------------------------------------------
__global__ void cwbl_finalize_kernel(float* __restrict__ out) {
    __shared__ double sd[256];
    double s = 0.0;
    for (int k = threadIdx.x; k < BQ * HQ; k += 256)
        s += (double)g_partial[k];
    sd[threadIdx.x] = s;
    __syncthreads();
#pragma unroll
    for (int st = 128; st > 0; st >>= 1) {
        if (threadIdx.x < st) sd[threadIdx.x] += sd[threadIdx.x + st];
        __syncthreads();
    }
    if (threadIdx.x == 0)
        out[0] = (float)(sd[0] / (3.0 * (double)NPIX));
}

// ---------------------------------------------------------------------------
extern "C" void kernel_launch(void* const* d_in, const int* in_sizes, int n_in,
                              void* d_out, int out_size) {
    const float* pred   = (const float*)d_in[0];
    const int*   target = (const int*)d_in[1];
    const float* wgt    = (const float*)d_in[2];
    float* out = (float*)d_out;
    (void)in_sizes; (void)n_in; (void)out_size;

    cwbl_counts_kernel<<<BQ, 256>>>(target);
    cwbl_main_kernel<<<BQ * HQ, 256>>>(pred, target, wgt);
    cwbl_finalize_kernel<<<1, 256>>>(out);
}

// round 5
// speedup vs baseline: 1.0044x; 1.0044x over previous
#include <cuda_runtime.h>

// Problem dims (fixed by the dataset): pred [8,4,256,256] f32, target [8,256,256] i32,
// boundary_weight [8,1,256,256] f32, output: scalar f32.
#define BQ 8
#define HQ 256
#define WQ 256
#define HWQ (HQ * WQ)
#define NPIX (BQ * HWQ)
#define BIGD2 (1 << 28)

// Scratch: __device__ globals only (harness-sanctioned). All fully overwritten
// every run -> no init kernel needed, fully deterministic.
__device__ int   g_counts[BQ * 3];     // pixel count of class c (c=1..3) per image
__device__ float g_partial[BQ * HQ];   // one partial sum per block of main kernel

// ---------------------------------------------------------------------------
// Kernel 1: per-image class counts (for degenerate-class detection).
// Grid: 8 blocks (one per image), 256 threads (one per column).
// Reads are fully coalesced (warp spans consecutive j at each row step).
// ---------------------------------------------------------------------------
__global__ void cwbl_counts_kernel(const int* __restrict__ target) {
    const int b = blockIdx.x;
    const int j = threadIdx.x;
    const int* tb = target + b * HWQ;

    int c1 = 0, c2 = 0, c3 = 0;
#pragma unroll 8
    for (int r = 0; r < HQ; ++r) {
        int v = tb[r * WQ + j];
        c1 += (v == 1);
        c2 += (v == 2);
        c3 += (v == 3);
    }
#pragma unroll
    for (int o = 16; o > 0; o >>= 1) {
        c1 += __shfl_down_sync(0xffffffffu, c1, o);
        c2 += __shfl_down_sync(0xffffffffu, c2, o);
        c3 += __shfl_down_sync(0xffffffffu, c3, o);
    }
    __shared__ int s1[8], s2[8], s3[8];
    const int wid = j >> 5, lid = j & 31;
    if (lid == 0) { s1[wid] = c1; s2[wid] = c2; s3[wid] = c3; }
    __syncthreads();
    if (j == 0) {
        int t1 = 0, t2 = 0, t3 = 0;
#pragma unroll
        for (int k = 0; k < 8; ++k) { t1 += s1[k]; t2 += s2[k]; t3 += s3[k]; }
        g_counts[b * 3 + 0] = t1;
        g_counts[b * 3 + 1] = t2;
        g_counts[b * 3 + 2] = t3;
    }
}

// ---------------------------------------------------------------------------
// Kernel 2: fused softmax + exact nearest-opposite-class distance (expanding
// Chebyshev-ring search) + weighted-error accumulation.
// Grid: 2048 blocks (one per (b, row i)), 256 threads (one per column j).
//
// Exactness: for output pixel p and class c,
//   dist_c(p) = edt(m_c)(p) + edt(~m_c)(p)
//             = sqrt(d2 to nearest pixel with target==c)   if target(p) != c
//             = sqrt(d2 to nearest pixel with target!=c)   if target(p) == c
// Ring r only contains pixels with d2 >= r*r, so once r*r >= every needed
// best-d2, the search is provably complete. Degenerate classes contribute 0
// and are excluded from the termination requirement.
// ---------------------------------------------------------------------------
__global__ void cwbl_main_kernel(const float* __restrict__ pred,
                                 const int*   __restrict__ target,
                                 const float* __restrict__ wgt) {
    const int bi = blockIdx.x;      // b*HQ + i
    const int b  = bi >> 8;
    const int i  = bi & (HQ - 1);
    const int j  = threadIdx.x;

    const int* tb  = target + b * HWQ;
    const int base = i * WQ + j;

    const int   t = tb[base];
    const float w = wgt[b * HWQ + base];

    // --- softmax over 4 channels ---
    const float* pb = pred + (size_t)b * 4 * HWQ;
    const float x0 = pb[base];
    const float x1 = pb[HWQ + base];
    const float x2 = pb[2 * HWQ + base];
    const float x3 = pb[3 * HWQ + base];
    const float mx = fmaxf(fmaxf(x0, x1), fmaxf(x2, x3));
    const float e0 = __expf(x0 - mx);
    const float e1 = __expf(x1 - mx);
    const float e2 = __expf(x2 - mx);
    const float e3 = __expf(x3 - mx);
    const float rd = 1.0f / (e0 + e1 + e2 + e3);

    // --- degenerate-class flags ---
    const int cnt1 = g_counts[b * 3 + 0];
    const int cnt2 = g_counts[b * 3 + 1];
    const int cnt3 = g_counts[b * 3 + 2];
    const bool deg1 = (cnt1 == 0) || (cnt1 == HWQ);
    const bool deg2 = (cnt2 == 0) || (cnt2 == HWQ);
    const bool deg3 = (cnt3 == 0) || (cnt3 == HWQ);

    // --- expanding ring search for nearest pixel of each class value ---
    int bd0 = BIGD2, bd1 = BIGD2, bd2 = BIGD2, bd3 = BIGD2;
    if      (t == 0) bd0 = 0;
    else if (t == 1) bd1 = 0;
    else if (t == 2) bd2 = 0;
    else             bd3 = 0;

#pragma unroll 1
    for (int r = 1; r < 256; ++r) {
        // nearest pixel of a class != t (needed when t is the class itself)
        int mo = BIGD2;
        if (t != 0) mo = min(mo, bd0);
        if (t != 1) mo = min(mo, bd1);
        if (t != 2) mo = min(mo, bd2);
        if (t != 3) mo = min(mo, bd3);

        int M = 0;
        if (!deg1) M = max(M, (t == 1) ? mo : bd1);
        if (!deg2) M = max(M, (t == 2) ? mo : bd2);
        if (!deg3) M = max(M, (t == 3) ? mo : bd3);
        if (r * r >= M) break;

        const int r2   = r * r;
        const int itop = i - r;
        const int ibot = i + r;
        const bool okT = (itop >= 0);
        const bool okB = (ibot < HQ);
        const int* rowT = tb + itop * WQ;
        const int* rowB = tb + ibot * WQ;

        // top & bottom rows of the ring
#pragma unroll 1
        for (int dj = -r; dj <= r; ++dj) {
            const int jj = j + dj;
            if ((unsigned)jj >= (unsigned)WQ) continue;
            const int d2 = r2 + dj * dj;
            if (okT) {
                const int v = __ldg(&rowT[jj]);
                bd0 = min(bd0, (v == 0) ? d2 : BIGD2);
                bd1 = min(bd1, (v == 1) ? d2 : BIGD2);
                bd2 = min(bd2, (v == 2) ? d2 : BIGD2);
                bd3 = min(bd3, (v == 3) ? d2 : BIGD2);
            }
            if (okB) {
                const int v = __ldg(&rowB[jj]);
                bd0 = min(bd0, (v == 0) ? d2 : BIGD2);
                bd1 = min(bd1, (v == 1) ? d2 : BIGD2);
                bd2 = min(bd2, (v == 2) ? d2 : BIGD2);
                bd3 = min(bd3, (v == 3) ? d2 : BIGD2);
            }
        }

        // left & right columns of the ring (excluding corners)
        const int jl = j - r;
        const int jr = j + r;
        const bool okL = (jl >= 0);
        const bool okR = (jr < WQ);
#pragma unroll 1
        for (int di = -r + 1; di <= r - 1; ++di) {
            const int ii = i + di;
            if ((unsigned)ii >= (unsigned)HQ) continue;
            const int d2  = di * di + r2;
            const int* row = tb + ii * WQ;
            if (okL) {
                const int v = __ldg(&row[jl]);
                bd0 = min(bd0, (v == 0) ? d2 : BIGD2);
                bd1 = min(bd1, (v == 1) ? d2 : BIGD2);
                bd2 = min(bd2, (v == 2) ? d2 : BIGD2);
                bd3 = min(bd3, (v == 3) ? d2 : BIGD2);
            }
            if (okR) {
                const int v = __ldg(&row[jr]);
                bd0 = min(bd0, (v == 0) ? d2 : BIGD2);
                bd1 = min(bd1, (v == 1) ? d2 : BIGD2);
                bd2 = min(bd2, (v == 2) ? d2 : BIGD2);
                bd3 = min(bd3, (v == 3) ? d2 : BIGD2);
            }
        }
    }

    // final min-over-others (for pixels whose own class is being scored)
    int mo = BIGD2;
    if (t != 0) mo = min(mo, bd0);
    if (t != 1) mo = min(mo, bd1);
    if (t != 2) mo = min(mo, bd2);
    if (t != 3) mo = min(mo, bd3);

    // --- loss contributions for classes 1..3 ---
    float acc = 0.0f;
    {
        const float dist = deg1 ? 0.0f : sqrtf((float)((t == 1) ? mo : bd1));
        const float tc = (t == 1) ? 1.0f : 0.0f;
        acc += fabsf(e1 * rd - tc) * dist;
    }
    {
        const float dist = deg2 ? 0.0f : sqrtf((float)((t == 2) ? mo : bd2));
        const float tc = (t == 2) ? 1.0f : 0.0f;
        acc += fabsf(e2 * rd - tc) * dist;
    }
    {
        const float dist = deg3 ? 0.0f : sqrtf((float)((t == 3) ? mo : bd3));
        const float tc = (t == 3) ? 1.0f : 0.0f;
        acc += fabsf(e3 * rd - tc) * dist;
    }
    acc *= w;

    // --- block reduction -> deterministic per-block partial (no atomics) ---
#pragma unroll
    for (int o = 16; o > 0; o >>= 1)
        acc += __shfl_down_sync(0xffffffffu, acc, o);
    __shared__ float sa[8];
    const int wid = j >> 5, lid = j & 31;
    if (lid == 0) sa[wid] = acc;
    __syncthreads();
    if (j == 0) {
        float s = 0.0f;
#pragma unroll
        for (int k = 0; k < 8; ++k) s += sa[k];
        g_partial[blockIdx.x] = s;
    }
}

// ---------------------------------------------------------------------------
// Kernel 3: deterministic final reduction of 2048 partials.
// ---------------------------------------------------------------------------
__global__ void cwbl_finalize_kernel(float* __restrict__ out) {
    __shared__ double sd[256];
    double s = 0.0;
    for (int k = threadIdx.x; k < BQ * HQ; k += 256)
        s += (double)g_partial[k];
    sd[threadIdx.x] = s;
    __syncthreads();
#pragma unroll
    for (int st = 128; st > 0; st >>= 1) {
        if (threadIdx.x < st) sd[threadIdx.x] += sd[threadIdx.x + st];
        __syncthreads();
    }
    if (threadIdx.x == 0)
        out[0] = (float)(sd[0] / (3.0 * (double)NPIX));
}

// ---------------------------------------------------------------------------
extern "C" void kernel_launch(void* const* d_in, const int* in_sizes, int n_in,
                              void* d_out, int out_size) {
    const float* pred   = (const float*)d_in[0];
    const int*   target = (const int*)d_in[1];
    const float* wgt    = (const float*)d_in[2];
    float* out = (float*)d_out;
    (void)in_sizes; (void)n_in; (void)out_size;

    cwbl_counts_kernel<<<BQ, 256>>>(target);
    cwbl_main_kernel<<<BQ * HQ, 256>>>(pred, target, wgt);
    cwbl_finalize_kernel<<<1, 256>>>(out);
}

// round 6
// speedup vs baseline: 1.2373x; 1.2319x over previous
#include <cuda_runtime.h>
#include <cstdint>

// Problem dims (fixed by the dataset): pred [8,4,256,256] f32, target [8,256,256] i32,
// boundary_weight [8,1,256,256] f32, output: scalar f32.
#define BQ 8
#define HQ 256
#define WQ 256
#define HWQ (HQ * WQ)
#define NPIX (BQ * HWQ)
#define BIGD2 (1 << 28)

// Scratch: __device__ globals only (harness-sanctioned).
// INVARIANT: g_counts is zero at entry to every kernel_launch call —
// zero-initialized at module load, and re-zeroed by the finalize kernel at the
// end of every run. Deterministic across correctness run / capture / replays.
__device__ int     g_counts[BQ * 3];   // pixel count of class c (c=1..3) per image
__device__ float   g_partial[BQ * HQ]; // one partial per block of main kernel
__device__ uint8_t g_tgt8[NPIX];       // byte-packed copy of target (4x denser in L1)

// ---------------------------------------------------------------------------
// Kernel 1: fused target byte-pack + per-image class counts.
// Grid: 512 blocks x 256 threads; each thread handles one int4 (4 pixels).
// Each block lies entirely within one image (1024 contiguous pixels).
// Counts accumulate via integer atomics (exact, order-independent).
// ---------------------------------------------------------------------------
__global__ void cwbl_pack_counts_kernel(const int* __restrict__ target) {
    const int idx = blockIdx.x * 256 + threadIdx.x;        // int4 index
    const int4 v  = ((const int4*)target)[idx];

    const unsigned pack = (unsigned)v.x | ((unsigned)v.y << 8) |
                          ((unsigned)v.z << 16) | ((unsigned)v.w << 24);
    ((unsigned*)g_tgt8)[idx] = pack;

    int c1 = (v.x == 1) + (v.y == 1) + (v.z == 1) + (v.w == 1);
    int c2 = (v.x == 2) + (v.y == 2) + (v.z == 2) + (v.w == 2);
    int c3 = (v.x == 3) + (v.y == 3) + (v.z == 3) + (v.w == 3);

#pragma unroll
    for (int o = 16; o > 0; o >>= 1) {
        c1 += __shfl_down_sync(0xffffffffu, c1, o);
        c2 += __shfl_down_sync(0xffffffffu, c2, o);
        c3 += __shfl_down_sync(0xffffffffu, c3, o);
    }
    __shared__ int s1[8], s2[8], s3[8];
    const int wid = threadIdx.x >> 5, lid = threadIdx.x & 31;
    if (lid == 0) { s1[wid] = c1; s2[wid] = c2; s3[wid] = c3; }
    __syncthreads();
    if (threadIdx.x == 0) {
        int t1 = 0, t2 = 0, t3 = 0;
#pragma unroll
        for (int k = 0; k < 8; ++k) { t1 += s1[k]; t2 += s2[k]; t3 += s3[k]; }
        const int b = blockIdx.x >> 6;   // 64 blocks per image
        atomicAdd(&g_counts[b * 3 + 0], t1);
        atomicAdd(&g_counts[b * 3 + 1], t2);
        atomicAdd(&g_counts[b * 3 + 2], t3);
    }
}

// ---------------------------------------------------------------------------
// Kernel 2: fused softmax + exact nearest-opposite-class distance (expanding
// Chebyshev-ring search over the byte-packed map) + weighted-error sum.
// Grid: 2048 blocks (one per (b, row i)), 256 threads (one per column j).
//
// Exactness: dist_c(p) = sqrt(d2 to nearest pixel with target==c) if t(p)!=c,
// else sqrt(d2 to nearest pixel with target!=c). Ring r only contains pixels
// with d2 >= r*r, so once r*r >= every needed best-d2 the search is complete.
// Degenerate classes contribute 0 and are excluded from termination.
// ---------------------------------------------------------------------------
__global__ void cwbl_main_kernel(const float* __restrict__ pred,
                                 const float* __restrict__ wgt) {
    const int bi = blockIdx.x;      // b*HQ + i
    const int b  = bi >> 8;
    const int i  = bi & (HQ - 1);
    const int j  = threadIdx.x;

    const uint8_t* tb = g_tgt8 + b * HWQ;
    const int base = i * WQ + j;

    const int   t = tb[base];
    const float w = wgt[b * HWQ + base];

    // --- softmax over 4 channels ---
    const float* pb = pred + (size_t)b * 4 * HWQ;
    const float x0 = pb[base];
    const float x1 = pb[HWQ + base];
    const float x2 = pb[2 * HWQ + base];
    const float x3 = pb[3 * HWQ + base];
    const float mx = fmaxf(fmaxf(x0, x1), fmaxf(x2, x3));
    const float e0 = __expf(x0 - mx);
    const float e1 = __expf(x1 - mx);
    const float e2 = __expf(x2 - mx);
    const float e3 = __expf(x3 - mx);
    const float rd = 1.0f / (e0 + e1 + e2 + e3);

    // --- degenerate-class flags ---
    const int cnt1 = g_counts[b * 3 + 0];
    const int cnt2 = g_counts[b * 3 + 1];
    const int cnt3 = g_counts[b * 3 + 2];
    const bool deg1 = (cnt1 == 0) || (cnt1 == HWQ);
    const bool deg2 = (cnt2 == 0) || (cnt2 == HWQ);
    const bool deg3 = (cnt3 == 0) || (cnt3 == HWQ);

    // --- expanding ring search for nearest pixel of each class value ---
    int bd0 = BIGD2, bd1 = BIGD2, bd2 = BIGD2, bd3 = BIGD2;
    if      (t == 0) bd0 = 0;
    else if (t == 1) bd1 = 0;
    else if (t == 2) bd2 = 0;
    else             bd3 = 0;

#pragma unroll 1
    for (int r = 1; r < 256; ++r) {
        // nearest pixel of a class != t (needed when scoring t's own class)
        int mo = BIGD2;
        if (t != 0) mo = min(mo, bd0);
        if (t != 1) mo = min(mo, bd1);
        if (t != 2) mo = min(mo, bd2);
        if (t != 3) mo = min(mo, bd3);

        int M = 0;
        if (!deg1) M = max(M, (t == 1) ? mo : bd1);
        if (!deg2) M = max(M, (t == 2) ? mo : bd2);
        if (!deg3) M = max(M, (t == 3) ? mo : bd3);
        if (r * r >= M) break;

        const int r2   = r * r;
        const int itop = i - r;
        const int ibot = i + r;
        const bool okT = (itop >= 0);
        const bool okB = (ibot < HQ);
        const uint8_t* rowT = tb + itop * WQ;
        const uint8_t* rowB = tb + ibot * WQ;

        // top & bottom rows of the ring
#pragma unroll 1
        for (int dj = -r; dj <= r; ++dj) {
            const int jj = j + dj;
            if ((unsigned)jj >= (unsigned)WQ) continue;
            const int d2 = r2 + dj * dj;
            if (okT) {
                const int v = __ldg(&rowT[jj]);
                bd0 = min(bd0, (v == 0) ? d2 : BIGD2);
                bd1 = min(bd1, (v == 1) ? d2 : BIGD2);
                bd2 = min(bd2, (v == 2) ? d2 : BIGD2);
                bd3 = min(bd3, (v == 3) ? d2 : BIGD2);
            }
            if (okB) {
                const int v = __ldg(&rowB[jj]);
                bd0 = min(bd0, (v == 0) ? d2 : BIGD2);
                bd1 = min(bd1, (v == 1) ? d2 : BIGD2);
                bd2 = min(bd2, (v == 2) ? d2 : BIGD2);
                bd3 = min(bd3, (v == 3) ? d2 : BIGD2);
            }
        }

        // left & right columns of the ring (excluding corners)
        const int jl = j - r;
        const int jr = j + r;
        const bool okL = (jl >= 0);
        const bool okR = (jr < WQ);
#pragma unroll 1
        for (int di = -r + 1; di <= r - 1; ++di) {
            const int ii = i + di;
            if ((unsigned)ii >= (unsigned)HQ) continue;
            const int d2  = di * di + r2;
            const uint8_t* row = tb + ii * WQ;
            if (okL) {
                const int v = __ldg(&row[jl]);
                bd0 = min(bd0, (v == 0) ? d2 : BIGD2);
                bd1 = min(bd1, (v == 1) ? d2 : BIGD2);
                bd2 = min(bd2, (v == 2) ? d2 : BIGD2);
                bd3 = min(bd3, (v == 3) ? d2 : BIGD2);
            }
            if (okR) {
                const int v = __ldg(&row[jr]);
                bd0 = min(bd0, (v == 0) ? d2 : BIGD2);
                bd1 = min(bd1, (v == 1) ? d2 : BIGD2);
                bd2 = min(bd2, (v == 2) ? d2 : BIGD2);
                bd3 = min(bd3, (v == 3) ? d2 : BIGD2);
            }
        }
    }

    // final min-over-others (for pixels whose own class is being scored)
    int mo = BIGD2;
    if (t != 0) mo = min(mo, bd0);
    if (t != 1) mo = min(mo, bd1);
    if (t != 2) mo = min(mo, bd2);
    if (t != 3) mo = min(mo, bd3);

    // --- loss contributions for classes 1..3 ---
    float acc = 0.0f;
    {
        const float dist = deg1 ? 0.0f : sqrtf((float)((t == 1) ? mo : bd1));
        const float tc = (t == 1) ? 1.0f : 0.0f;
        acc += fabsf(e1 * rd - tc) * dist;
    }
    {
        const float dist = deg2 ? 0.0f : sqrtf((float)((t == 2) ? mo : bd2));
        const float tc = (t == 2) ? 1.0f : 0.0f;
        acc += fabsf(e2 * rd - tc) * dist;
    }
    {
        const float dist = deg3 ? 0.0f : sqrtf((float)((t == 3) ? mo : bd3));
        const float tc = (t == 3) ? 1.0f : 0.0f;
        acc += fabsf(e3 * rd - tc) * dist;
    }
    acc *= w;

    // --- block reduction -> deterministic per-block partial (no atomics) ---
#pragma unroll
    for (int o = 16; o > 0; o >>= 1)
        acc += __shfl_down_sync(0xffffffffu, acc, o);
    __shared__ float sa[8];
    const int wid = j >> 5, lid = j & 31;
    if (lid == 0) sa[wid] = acc;
    __syncthreads();
    if (j == 0) {
        float s = 0.0f;
#pragma unroll
        for (int k = 0; k < 8; ++k) s += sa[k];
        g_partial[blockIdx.x] = s;
    }
}

// ---------------------------------------------------------------------------
// Kernel 3: deterministic final reduction of 2048 partials.
// Also re-zeroes g_counts so the next kernel_launch call starts from the same
// state (matches the module-load zero-init of the very first call).
// ---------------------------------------------------------------------------
__global__ void cwbl_finalize_kernel(float* __restrict__ out) {
    __shared__ double sd[256];
    double s = 0.0;
    for (int k = threadIdx.x; k < BQ * HQ; k += 256)
        s += (double)g_partial[k];
    sd[threadIdx.x] = s;
    __syncthreads();
#pragma unroll
    for (int st = 128; st > 0; st >>= 1) {
        if (threadIdx.x < st) sd[threadIdx.x] += sd[threadIdx.x + st];
        __syncthreads();
    }
    if (threadIdx.x == 0)
        out[0] = (float)(sd[0] / (3.0 * (double)NPIX));
    // reset counts for the next run (deterministic invariant)
    if (threadIdx.x < BQ * 3)
        g_counts[threadIdx.x] = 0;
}

// ---------------------------------------------------------------------------
extern "C" void kernel_launch(void* const* d_in, const int* in_sizes, int n_in,
                              void* d_out, int out_size) {
    const float* pred   = (const float*)d_in[0];
    const int*   target = (const int*)d_in[1];
    const float* wgt    = (const float*)d_in[2];
    float* out = (float*)d_out;
    (void)in_sizes; (void)n_in; (void)out_size;

    cwbl_pack_counts_kernel<<<NPIX / 1024, 256>>>(target);
    cwbl_main_kernel<<<BQ * HQ, 256>>>(pred, wgt);
    cwbl_finalize_kernel<<<1, 256>>>(out);
}

// round 7
// speedup vs baseline: 1.6598x; 1.3414x over previous
#include <cuda_runtime.h>
#include <cstdint>

// Problem dims (fixed): pred [8,4,256,256] f32, target [8,256,256] i32,
// boundary_weight [8,1,256,256] f32, output: scalar f32.
#define BQ 8
#define HQ 256
#define WQ 256
#define HWQ (HQ * WQ)
#define NPIX (BQ * HWQ)
#define NBLK (BQ * HQ)
#define BIGD2 (1 << 28)

// Scratch: __device__ globals only (harness-sanctioned).
// g_done is zero at module load; the last block resets it to 0 after the
// final reduction, so every kernel_launch call (correctness, capture, each
// replay) starts from identical state -> fully deterministic.
__device__ float    g_partial[NBLK];
__device__ unsigned g_done;

// ---------------------------------------------------------------------------
// Single fused kernel. Grid: 2048 blocks (one per (b,row i)), 256 threads
// (one per column j).
//
// dist_c(p) = sqrt(d2 to nearest pixel with target==c)  if t(p) != c
//           = sqrt(d2 to nearest pixel with target!=c)  if t(p) == c
// and contributes 0 if no such pixel exists anywhere (this reproduces the
// reference's degenerate-class zeroing: class absent -> never found; class
// covering the whole image -> "nearest other" never found).
//
// Phase 1: branch-free 5x5 window scan from smem (sentinel-padded, fully
//          unrolled, compile-time d2 constants). Exact for any best-d2 <= 8,
//          because every pixel outside the window has d2 >= 9.
// Phase 2 (rare, ~0.3% of pixels): expanding Chebyshev-ring search starting
//          at r=3 (rings r cover exactly the pixels with d2 in [r^2, 2r^2]),
//          terminating when r^2 >= every still-needed best-d2.
// Epilogue: softmax, |p_c - t_c| * w * dist_c, block reduction, and a
//          last-block deterministic final reduction (ticket + threadfence).
// ---------------------------------------------------------------------------
__global__ __launch_bounds__(256) void cwbl_kernel(
        const float* __restrict__ pred,
        const int*   __restrict__ target,
        const float* __restrict__ wgt,
        float*       __restrict__ out) {
    const int bi = blockIdx.x;       // b*HQ + i
    const int b  = bi >> 8;
    const int i  = bi & (HQ - 1);
    const int j  = threadIdx.x;

    const int* tb   = target + b * HWQ;
    const int  base = i * WQ + j;

    // Kick off the independent float loads early (overlap with smem fill).
    const float w = wgt[b * HWQ + base];
    const float* pb = pred + (size_t)b * 4 * HWQ;
    const float x0 = pb[base];
    const float x1 = pb[HWQ + base];
    const float x2 = pb[2 * HWQ + base];
    const float x3 = pb[3 * HWQ + base];

    // --- smem tile: rows i-2..i+2, byte-packed, 2-byte sentinel pads ---
    __shared__ uint8_t srow[5][264];   // columns used: [0, 260); pads = 0xFF
#pragma unroll
    for (int k = 0; k < 5; ++k) {
        const int ii = i + k - 2;
        if ((unsigned)ii < (unsigned)HQ) {            // uniform per block
            srow[k][j + 2] = (uint8_t)__ldg(&tb[ii * WQ + j]);
            if (j < 2) { srow[k][j] = 0xFF; srow[k][258 + j] = 0xFF; }
        }
    }
    __syncthreads();

    const int t = srow[2][j + 2];      // own class (row k=2 is always valid)

    // --- Phase 1: branch-free 5x5 window scan ---
    int bd0 = BIGD2, bd1 = BIGD2, bd2 = BIGD2, bd3 = BIGD2;
#pragma unroll
    for (int k = 0; k < 5; ++k) {
        const int ii = i + k - 2;
        if ((unsigned)ii >= (unsigned)HQ) continue;   // uniform per block
        const int di = k - 2;
#pragma unroll
        for (int dj = -2; dj <= 2; ++dj) {
            const int d2 = di * di + dj * dj;         // compile-time const
            const int v  = srow[k][j + 2 + dj];       // 0xFF pad never matches
            bd0 = min(bd0, v == 0 ? d2 : BIGD2);
            bd1 = min(bd1, v == 1 ? d2 : BIGD2);
            bd2 = min(bd2, v == 2 ? d2 : BIGD2);
            bd3 = min(bd3, v == 3 ? d2 : BIGD2);
        }
    }

    // needed values so far
    int mo = BIGD2;
    if (t != 0) mo = min(mo, bd0);
    if (t != 1) mo = min(mo, bd1);
    if (t != 2) mo = min(mo, bd2);
    if (t != 3) mo = min(mo, bd3);
    int n1 = (t == 1) ? mo : bd1;
    int n2 = (t == 2) ? mo : bd2;
    int n3 = (t == 3) ? mo : bd3;

    // --- Phase 2: rare exact fallback (window guarantee is d2 <= 8) ---
    if (max(n1, max(n2, n3)) > 8) {
#pragma unroll 1
        for (int r = 3; r < 256; ++r) {
            int mo_ = BIGD2;
            if (t != 0) mo_ = min(mo_, bd0);
            if (t != 1) mo_ = min(mo_, bd1);
            if (t != 2) mo_ = min(mo_, bd2);
            if (t != 3) mo_ = min(mo_, bd3);
            int M = 0;
            M = max(M, (t == 1) ? mo_ : bd1);
            M = max(M, (t == 2) ? mo_ : bd2);
            M = max(M, (t == 3) ? mo_ : bd3);
            if (r * r >= M) break;

            const int r2   = r * r;
            const int itop = i - r;
            const int ibot = i + r;
            const bool okT = (itop >= 0);
            const bool okB = (ibot < HQ);
            const int* rowT = tb + itop * WQ;
            const int* rowB = tb + ibot * WQ;

#pragma unroll 1
            for (int dj = -r; dj <= r; ++dj) {
                const int jj = j + dj;
                if ((unsigned)jj >= (unsigned)WQ) continue;
                const int d2 = r2 + dj * dj;
                if (okT) {
                    const int v = __ldg(&rowT[jj]);
                    bd0 = min(bd0, (v == 0) ? d2 : BIGD2);
                    bd1 = min(bd1, (v == 1) ? d2 : BIGD2);
                    bd2 = min(bd2, (v == 2) ? d2 : BIGD2);
                    bd3 = min(bd3, (v == 3) ? d2 : BIGD2);
                }
                if (okB) {
                    const int v = __ldg(&rowB[jj]);
                    bd0 = min(bd0, (v == 0) ? d2 : BIGD2);
                    bd1 = min(bd1, (v == 1) ? d2 : BIGD2);
                    bd2 = min(bd2, (v == 2) ? d2 : BIGD2);
                    bd3 = min(bd3, (v == 3) ? d2 : BIGD2);
                }
            }
            const int jl = j - r;
            const int jr = j + r;
            const bool okL = (jl >= 0);
            const bool okR = (jr < WQ);
#pragma unroll 1
            for (int di = -r + 1; di <= r - 1; ++di) {
                const int ii = i + di;
                if ((unsigned)ii >= (unsigned)HQ) continue;
                const int d2  = di * di + r2;
                const int* row = tb + ii * WQ;
                if (okL) {
                    const int v = __ldg(&row[jl]);
                    bd0 = min(bd0, (v == 0) ? d2 : BIGD2);
                    bd1 = min(bd1, (v == 1) ? d2 : BIGD2);
                    bd2 = min(bd2, (v == 2) ? d2 : BIGD2);
                    bd3 = min(bd3, (v == 3) ? d2 : BIGD2);
                }
                if (okR) {
                    const int v = __ldg(&row[jr]);
                    bd0 = min(bd0, (v == 0) ? d2 : BIGD2);
                    bd1 = min(bd1, (v == 1) ? d2 : BIGD2);
                    bd2 = min(bd2, (v == 2) ? d2 : BIGD2);
                    bd3 = min(bd3, (v == 3) ? d2 : BIGD2);
                }
            }
        }
        mo = BIGD2;
        if (t != 0) mo = min(mo, bd0);
        if (t != 1) mo = min(mo, bd1);
        if (t != 2) mo = min(mo, bd2);
        if (t != 3) mo = min(mo, bd3);
        n1 = (t == 1) ? mo : bd1;
        n2 = (t == 2) ? mo : bd2;
        n3 = (t == 3) ? mo : bd3;
    }

    // --- softmax ---
    const float mx = fmaxf(fmaxf(x0, x1), fmaxf(x2, x3));
    const float e0 = __expf(x0 - mx);
    const float e1 = __expf(x1 - mx);
    const float e2 = __expf(x2 - mx);
    const float e3 = __expf(x3 - mx);
    const float rd = 1.0f / (e0 + e1 + e2 + e3);

    // --- loss contributions (unfound => dist 0, reproducing degeneracy) ---
    float acc;
    {
        const float d1 = (n1 < BIGD2) ? sqrtf((float)n1) : 0.0f;
        const float d2f = (n2 < BIGD2) ? sqrtf((float)n2) : 0.0f;
        const float d3 = (n3 < BIGD2) ? sqrtf((float)n3) : 0.0f;
        acc  = fabsf(e1 * rd - ((t == 1) ? 1.0f : 0.0f)) * d1;
        acc += fabsf(e2 * rd - ((t == 2) ? 1.0f : 0.0f)) * d2f;
        acc += fabsf(e3 * rd - ((t == 3) ? 1.0f : 0.0f)) * d3;
        acc *= w;
    }

    // --- block reduction -> per-block partial (fixed order) ---
#pragma unroll
    for (int o = 16; o > 0; o >>= 1)
        acc += __shfl_down_sync(0xffffffffu, acc, o);
    __shared__ float sa[8];
    const int wid = j >> 5, lid = j & 31;
    if (lid == 0) sa[wid] = acc;
    __syncthreads();
    if (j == 0) {
        float s = 0.0f;
#pragma unroll
        for (int k = 0; k < 8; ++k) s += sa[k];
        g_partial[bi] = s;
    }

    // --- last-block deterministic finalize (saves a kernel launch) ---
    __shared__ unsigned ticket;
    __threadfence();
    if (j == 0) ticket = atomicAdd(&g_done, 1u);
    __syncthreads();
    if (ticket == NBLK - 1) {
        __threadfence();
        __shared__ double sd[256];
        double s = 0.0;
        for (int k = j; k < NBLK; k += 256)
            s += (double)g_partial[k];              // fixed stride order
        sd[j] = s;
        __syncthreads();
#pragma unroll
        for (int st = 128; st > 0; st >>= 1) {
            if (j < st) sd[j] += sd[j + st];
            __syncthreads();
        }
        if (j == 0) {
            out[0] = (float)(sd[0] / (3.0 * (double)NPIX));
            g_done = 0;                             // restore invariant
        }
    }
}

// ---------------------------------------------------------------------------
extern "C" void kernel_launch(void* const* d_in, const int* in_sizes, int n_in,
                              void* d_out, int out_size) {
    const float* pred   = (const float*)d_in[0];
    const int*   target = (const int*)d_in[1];
    const float* wgt    = (const float*)d_in[2];
    float* out = (float*)d_out;
    (void)in_sizes; (void)n_in; (void)out_size;

    cwbl_kernel<<<NBLK, 256>>>(pred, target, wgt, out);
}

// round 8
// speedup vs baseline: 2.5533x; 1.5383x over previous
#include <cuda_runtime.h>
#include <cstdint>

// Problem dims (fixed): pred [8,4,256,256] f32, target [8,256,256] i32,
// boundary_weight [8,1,256,256] f32, output: scalar f32.
#define BQ 8
#define HQ 256
#define WQ 256
#define HWQ (HQ * WQ)
#define NPIX (BQ * HWQ)
#define ROWS_PER_BLK 4
#define NBLK (NPIX / (ROWS_PER_BLK * WQ))   // 512 blocks
#define BIGD2 (1 << 28)

// __device__ globals only (harness-sanctioned). g_done is zero at module load
// and restored to zero by the last block every run -> identical state for the
// correctness run, the capture run, and every graph replay.
__device__ float    g_partial[NBLK];
__device__ unsigned g_done;

// ---------------------------------------------------------------------------
// Single fused kernel. Grid: 512 blocks; block = 256 threads = one column
// each, covering FOUR consecutive image rows i0..i0+3 of one image.
//
// dist_c(p) = sqrt(d2 to nearest pixel with target==c)  if t(p) != c
//           = sqrt(d2 to nearest pixel with target!=c)  if t(p) == c
// contributing 0 if no such pixel exists (reproduces the reference's
// degenerate-class zeroing).
//
// Phase 0: two ballot-built bitplanes per row (class = 2 bits/pixel).
// Phase 1: per target-row k and class c, a 7-bit window mask (2 funnel
//          shifts + 1 LOP3) -> smem LUT -> min dj^2; shared across the 4
//          pixel rows. Vertical combine over 7 rows with DPX
//          __viaddmin_u16x2 (2 classes per instruction).
//          Exact whenever best d2 <= 16 (everything outside the 7x7 box has
//          d2 >= 16). Miss probability ~0.75^48 ~ 1e-6 per pixel.
// Phase 2: per-pixel exact ring fallback from r=4 (covers all d2>=16),
//          with window results >18 discarded as uncertified.
// Epilogue: softmax + |p_c - t_c| * w * dist_c, block reduction, last-block
//          deterministic finalize.
// ---------------------------------------------------------------------------
__global__ __launch_bounds__(256) void cwbl_kernel(
        const float* __restrict__ pred,
        const int*   __restrict__ target,
        const float* __restrict__ wgt,
        float*       __restrict__ out) {
    const int blk = blockIdx.x;
    const int b   = blk >> 6;                    // 64 blocks per image
    const int i0  = (blk & 63) * ROWS_PER_BLK;
    const int j   = threadIdx.x;                 // column
    const int w   = j >> 5;                      // warp = word index
    const int l   = j & 31;                      // lane = bit index

    const int* tb = target + b * HWQ;

    __shared__ unsigned sb0[10][10], sb1[10][10];  // [row][word+1], sentinel cols
    __shared__ uint8_t  slut[128];                 // 7-bit mask -> min dj^2
    __shared__ float    sa[8];

    if (j < 128) {
        const int m = j;
        slut[m] = (m & 0x08) ? 0 : (m & 0x14) ? 1 : (m & 0x22) ? 4
                                 : (m & 0x41) ? 9 : 64;   // 64 = not found
    }
    if (j < 10) { sb0[j][0] = 0; sb1[j][0] = 0; sb0[j][9] = 0; sb1[j][9] = 0; }

    // --- Phase 0: bitplanes for rows i0-3 .. i0+6 (row validity handled later)
#pragma unroll
    for (int k = 0; k < 10; ++k) {
        const int ii  = i0 - 3 + k;
        const int iic = min(HQ - 1, max(0, ii));          // clamped (safe load)
        const int v   = __ldg(&tb[iic * WQ + j]);
        const unsigned m0 = __ballot_sync(0xffffffffu, v & 1);
        const unsigned m1 = __ballot_sync(0xffffffffu, v & 2);
        if (l == 0) { sb0[k][w + 1] = m0; sb1[k][w + 1] = m1; }
    }
    __syncthreads();

    // column-validity mask for the 7-bit window (bit k <-> dj = k-3)
    const int sl = max(0, 3 - j);
    const int sr = max(0, j - (WQ - 4));
    const unsigned vwin = ((0x7Fu << sl) & (0x7Fu >> sr)) & 0x7Fu;

    // --- Phase 1a: per-row horizontal min-dj^2, packed 2 classes per u16x2
    unsigned Dlo[10], Dhi[10];   // Dlo = cls0|cls1<<16, Dhi = cls2|cls3<<16
    unsigned t0bits = 0, t1bits = 0;   // own-pixel class bits per pixel row
#pragma unroll
    for (int k = 0; k < 10; ++k) {
        const unsigned p0 = sb0[k][w], c0 = sb0[k][w + 1], n0 = sb0[k][w + 2];
        const unsigned p1 = sb1[k][w], c1 = sb1[k][w + 1], q1 = sb1[k][w + 2];
        const unsigned w0 = (l < 3) ? __funnelshift_r(p0, c0, l + 29)
                                    : __funnelshift_r(c0, n0, l - 3);
        const unsigned w1 = (l < 3) ? __funnelshift_r(p1, c1, l + 29)
                                    : __funnelshift_r(c1, q1, l - 3);
        const unsigned mm0 = (~w0 & ~w1) & vwin;   // one LOP3 each
        const unsigned mm1 = ( w0 & ~w1) & vwin;
        const unsigned mm2 = (~w0 &  w1) & vwin;
        const unsigned mm3 = ( w0 &  w1) & vwin;
        const unsigned d0 = slut[mm0], d1 = slut[mm1];
        const unsigned d2 = slut[mm2], d3 = slut[mm3];
        const bool rv = ((unsigned)(i0 - 3 + k) < (unsigned)HQ);  // uniform
        Dlo[k] = rv ? (d0 | (d1 << 16)) : 0x00400040u;
        Dhi[k] = rv ? (d2 | (d3 << 16)) : 0x00400040u;
        if (k >= 3 && k <= 6) {           // own class bits for pixel row k-3
            t0bits |= ((w0 >> 3) & 1u) << (k - 3);
            t1bits |= ((w1 >> 3) & 1u) << (k - 3);
        }
    }

    const unsigned DD[7] = {0x00090009u, 0x00040004u, 0x00010001u, 0u,
                            0x00010001u, 0x00040004u, 0x00090009u};

    float acc = 0.0f;
    const float* pb = pred + (size_t)b * 4 * HWQ;

#pragma unroll
    for (int pr = 0; pr < ROWS_PER_BLK; ++pr) {
        // --- Phase 1b: vertical combine, DPX min(a+b, c) on u16x2
        unsigned blo = 0x00FF00FFu, bhi = 0x00FF00FFu;
#pragma unroll
        for (int q = 0; q < 7; ++q) {
            blo = __viaddmin_u16x2(Dlo[pr + q], DD[q], blo);
            bhi = __viaddmin_u16x2(Dhi[pr + q], DD[q], bhi);
        }
        int bd0 = (int)(blo & 0xFFFFu), bd1 = (int)(blo >> 16);
        int bd2 = (int)(bhi & 0xFFFFu), bd3 = (int)(bhi >> 16);
        const int t = (int)((t0bits >> pr) & 1u) | ((int)((t1bits >> pr) & 1u) << 1);

        int mo = min(min((t == 0) ? BIGD2 : bd0, (t == 1) ? BIGD2 : bd1),
                     min((t == 2) ? BIGD2 : bd2, (t == 3) ? BIGD2 : bd3));
        int n1 = (t == 1) ? mo : bd1;
        int n2 = (t == 2) ? mo : bd2;
        int n3 = (t == 3) ? mo : bd3;

        // --- Phase 2: rare exact fallback (window certifies only d2 <= 16)
        if (max(n1, max(n2, n3)) > 16) {
            bd0 = (bd0 > 18) ? BIGD2 : bd0;
            bd1 = (bd1 > 18) ? BIGD2 : bd1;
            bd2 = (bd2 > 18) ? BIGD2 : bd2;
            bd3 = (bd3 > 18) ? BIGD2 : bd3;
            const int i = i0 + pr;
#pragma unroll 1
            for (int r = 4; r < 256; ++r) {
                int mo_ = BIGD2;
                if (t != 0) mo_ = min(mo_, bd0);
                if (t != 1) mo_ = min(mo_, bd1);
                if (t != 2) mo_ = min(mo_, bd2);
                if (t != 3) mo_ = min(mo_, bd3);
                int M = 0;
                M = max(M, (t == 1) ? mo_ : bd1);
                M = max(M, (t == 2) ? mo_ : bd2);
                M = max(M, (t == 3) ? mo_ : bd3);
                if (r * r >= M) break;

                const int r2   = r * r;
                const int itop = i - r;
                const int ibot = i + r;
                const bool okT = (itop >= 0);
                const bool okB = (ibot < HQ);
                const int* rowT = tb + itop * WQ;
                const int* rowB = tb + ibot * WQ;
#pragma unroll 1
                for (int dj = -r; dj <= r; ++dj) {
                    const int jj = j + dj;
                    if ((unsigned)jj >= (unsigned)WQ) continue;
                    const int d2 = r2 + dj * dj;
                    if (okT) {
                        const int v = __ldg(&rowT[jj]);
                        bd0 = min(bd0, (v == 0) ? d2 : BIGD2);
                        bd1 = min(bd1, (v == 1) ? d2 : BIGD2);
                        bd2 = min(bd2, (v == 2) ? d2 : BIGD2);
                        bd3 = min(bd3, (v == 3) ? d2 : BIGD2);
                    }
                    if (okB) {
                        const int v = __ldg(&rowB[jj]);
                        bd0 = min(bd0, (v == 0) ? d2 : BIGD2);
                        bd1 = min(bd1, (v == 1) ? d2 : BIGD2);
                        bd2 = min(bd2, (v == 2) ? d2 : BIGD2);
                        bd3 = min(bd3, (v == 3) ? d2 : BIGD2);
                    }
                }
                const int jl = j - r;
                const int jr = j + r;
                const bool okL = (jl >= 0);
                const bool okR = (jr < WQ);
#pragma unroll 1
                for (int di = -r + 1; di <= r - 1; ++di) {
                    const int ii = i + di;
                    if ((unsigned)ii >= (unsigned)HQ) continue;
                    const int d2  = di * di + r2;
                    const int* row = tb + ii * WQ;
                    if (okL) {
                        const int v = __ldg(&row[jl]);
                        bd0 = min(bd0, (v == 0) ? d2 : BIGD2);
                        bd1 = min(bd1, (v == 1) ? d2 : BIGD2);
                        bd2 = min(bd2, (v == 2) ? d2 : BIGD2);
                        bd3 = min(bd3, (v == 3) ? d2 : BIGD2);
                    }
                    if (okR) {
                        const int v = __ldg(&row[jr]);
                        bd0 = min(bd0, (v == 0) ? d2 : BIGD2);
                        bd1 = min(bd1, (v == 1) ? d2 : BIGD2);
                        bd2 = min(bd2, (v == 2) ? d2 : BIGD2);
                        bd3 = min(bd3, (v == 3) ? d2 : BIGD2);
                    }
                }
            }
            mo = BIGD2;
            if (t != 0) mo = min(mo, bd0);
            if (t != 1) mo = min(mo, bd1);
            if (t != 2) mo = min(mo, bd2);
            if (t != 3) mo = min(mo, bd3);
            n1 = (t == 1) ? mo : bd1;
            n2 = (t == 2) ? mo : bd2;
            n3 = (t == 3) ? mo : bd3;
        }

        // --- epilogue: softmax + weighted error ---
        const int base = (i0 + pr) * WQ + j;
        const float wv = wgt[b * HWQ + base];
        const float x0 = pb[base];
        const float x1 = pb[HWQ + base];
        const float x2 = pb[2 * HWQ + base];
        const float x3 = pb[3 * HWQ + base];
        const float mx = fmaxf(fmaxf(x0, x1), fmaxf(x2, x3));
        const float e0 = __expf(x0 - mx);
        const float e1 = __expf(x1 - mx);
        const float e2 = __expf(x2 - mx);
        const float e3 = __expf(x3 - mx);
        const float rd = 1.0f / (e0 + e1 + e2 + e3);

        const float d1f = (n1 < BIGD2) ? sqrtf((float)n1) : 0.0f;
        const float d2f = (n2 < BIGD2) ? sqrtf((float)n2) : 0.0f;
        const float d3f = (n3 < BIGD2) ? sqrtf((float)n3) : 0.0f;
        float s = fabsf(e1 * rd - ((t == 1) ? 1.0f : 0.0f)) * d1f;
        s      += fabsf(e2 * rd - ((t == 2) ? 1.0f : 0.0f)) * d2f;
        s      += fabsf(e3 * rd - ((t == 3) ? 1.0f : 0.0f)) * d3f;
        acc += s * wv;
    }

    // --- block reduction -> per-block partial (fixed order, no atomics) ---
#pragma unroll
    for (int o = 16; o > 0; o >>= 1)
        acc += __shfl_down_sync(0xffffffffu, acc, o);
    if (l == 0) sa[w] = acc;
    __syncthreads();
    if (j == 0) {
        float s = 0.0f;
#pragma unroll
        for (int k = 0; k < 8; ++k) s += sa[k];
        g_partial[blk] = s;
    }

    // --- last-block deterministic finalize ---
    __shared__ unsigned ticket;
    __threadfence();
    if (j == 0) ticket = atomicAdd(&g_done, 1u);
    __syncthreads();
    if (ticket == NBLK - 1) {
        __threadfence();
        __shared__ double sd[256];
        double s = 0.0;
        for (int k = j; k < NBLK; k += 256)
            s += (double)g_partial[k];              // fixed order
        sd[j] = s;
        __syncthreads();
#pragma unroll
        for (int st = 128; st > 0; st >>= 1) {
            if (j < st) sd[j] += sd[j + st];
            __syncthreads();
        }
        if (j == 0) {
            out[0] = (float)(sd[0] / (3.0 * (double)NPIX));
            g_done = 0;                             // restore invariant
        }
    }
}

// ---------------------------------------------------------------------------
extern "C" void kernel_launch(void* const* d_in, const int* in_sizes, int n_in,
                              void* d_out, int out_size) {
    const float* pred   = (const float*)d_in[0];
    const int*   target = (const int*)d_in[1];
    const float* wgt    = (const float*)d_in[2];
    float* out = (float*)d_out;
    (void)in_sizes; (void)n_in; (void)out_size;

    cwbl_kernel<<<NBLK, 256>>>(pred, target, wgt, out);
}